// round 3
// baseline (speedup 1.0000x reference)
#include <cuda_runtime.h>

#define NN  50000
#define EE  1600000
#define FIN 1433
#define HID 64
#define CC  5000

// ---------------- scratch layout (floats) ----------------
#define OFF_AGG   0                         // [NN*64]  fine aggregation (zeroed)
#define OFF_XC    3200000                   // [CC*64]  pooled sums       (zeroed)
#define OFF_AGGC  3520000                   // [CC*64]  coarse agg        (zeroed)
#define OFF_DEGF  3840000                   // [NN]     fine in-degree    (zeroed)
#define OFF_DEGC  3890000                   // [CC]     coarse in-degree  (zeroed)
#define OFF_CNT   3895000                   // [CC]     cluster counts    (zeroed)
#define ZERO_TOT  3900000
#define OFF_H0    3900000                   // [NN*64]  x @ W_enc
#define OFF_DINVF 7100000                   // [NN]
#define OFF_IDEGF 7150000                   // [NN]
#define OFF_DINVC 7200000                   // [CC]
#define OFF_IDEGC 7205000                   // [CC]
#define OFF_ICNT  7210000                   // [CC]
#define OFF_TMPC  7215000                   // [CC*64]  coarse propagate out
#define OFF_XD    7535000                   // [CC*FIN] decoded coarse features
#define TOTAL_F   14700000                  // ~58.8 MB

__device__ __align__(128) float g_buf[TOTAL_F];
__device__ __align__(128) int   g_ei[2 * EE];   // converted int32 edge index
__device__ __align__(128) int   g_cl[NN];       // converted int32 cluster
__device__ int g_is64;                          // 1 if inputs are int64

// non-returning vector reduction to global (L2 atomic, 16B)
__device__ __forceinline__ void red4(float* p, float4 v) {
    asm volatile("red.global.add.v4.f32 [%0], {%1,%2,%3,%4};"
                 :: "l"(p), "f"(v.x), "f"(v.y), "f"(v.z), "f"(v.w) : "memory");
}

// ---------------- dtype sniff: int64 layout has zero high words ----------------
__global__ void detect_kernel(const int* __restrict__ ei_raw) {
    if (threadIdx.x == 0 && blockIdx.x == 0) {
        int all_zero = 1;
        for (int k = 0; k < 64; k++) {
            if (ei_raw[2 * k + 1] != 0) { all_zero = 0; break; }
        }
        g_is64 = all_zero;
    }
}

__global__ void convert_edges_kernel(const int* __restrict__ ei_raw) {
    int i = blockIdx.x * blockDim.x + threadIdx.x;
    if (i >= 2 * EE) return;
    int f = g_is64;
    g_ei[i] = f ? ei_raw[2 * i] : ei_raw[i];
}

__global__ void convert_cluster_kernel(const int* __restrict__ cl_raw) {
    int i = blockIdx.x * blockDim.x + threadIdx.x;
    if (i >= NN) return;
    int f = g_is64;
    g_cl[i] = f ? cl_raw[2 * i] : cl_raw[i];
}

// ---------------- zero scratch ----------------
__global__ void zero_kernel() {
    int i = blockIdx.x * blockDim.x + threadIdx.x;
    if (i < ZERO_TOT / 4) {
        ((float4*)g_buf)[i] = make_float4(0.f, 0.f, 0.f, 0.f);
    }
}

// ---------------- degree counting (4 edges/thread, vector load) ----------------
__global__ void count_edges_kernel() {
    int t = blockIdx.x * blockDim.x + threadIdx.x;
    int e0 = t * 4;
    if (e0 >= EE) return;
    int4 d4 = *(const int4*)&g_ei[EE + e0];   // EE%4==0 so aligned
    atomicAdd(&g_buf[OFF_DEGF + d4.x], 1.0f);
    atomicAdd(&g_buf[OFF_DEGF + d4.y], 1.0f);
    atomicAdd(&g_buf[OFF_DEGF + d4.z], 1.0f);
    atomicAdd(&g_buf[OFF_DEGF + d4.w], 1.0f);
}

// deg_c[c] = sum over nodes in c of deg_f  (== count of edges with cluster[dst]==c)
__global__ void node_pass_kernel() {
    int i = blockIdx.x * blockDim.x + threadIdx.x;
    if (i >= NN) return;
    int c = g_cl[i];
    atomicAdd(&g_buf[OFF_DEGC + c], g_buf[OFF_DEGF + i]);
    atomicAdd(&g_buf[OFF_CNT + c], 1.0f);
}

__global__ void prep_kernel() {
    int i = blockIdx.x * blockDim.x + threadIdx.x;
    if (i < NN) {
        float deg = g_buf[OFF_DEGF + i] + 1.0f;
        g_buf[OFF_DINVF + i] = rsqrtf(deg);
        g_buf[OFF_IDEGF + i] = 1.0f / deg;
    }
    if (i < CC) {
        float degc = g_buf[OFF_DEGC + i] + 1.0f;
        g_buf[OFF_DINVC + i] = rsqrtf(degc);
        g_buf[OFF_IDEGC + i] = 1.0f / degc;
        g_buf[OFF_ICNT + i]  = 1.0f / fmaxf(g_buf[OFF_CNT + i], 1.0f);
    }
}

// ---------------- GEMM1: h0[N,64] = x[N,1433] @ W_enc[1433,64] ----------------
// 128x64 tile, BK=16, 256 threads, 8x4 acc/thread
#define G1_BM 128
#define G1_BK 16
#define G1_KFULL 1424          // largest multiple of 16 <= 1433
__global__ void __launch_bounds__(256, 2) gemm1_kernel(const float* __restrict__ A,
                                                       const float* __restrict__ B) {
    __shared__ float As[G1_BK][G1_BM + 4];   // transposed: As[k][m]
    __shared__ float Bs[G1_BK][HID];
    float* Cout = g_buf + OFF_H0;

    int tid = threadIdx.x;                   // 256 threads
    int tx = tid & 15;                       // 16 col-groups of 4
    int ty = tid >> 4;                       // 16 row-groups of 8
    int m0 = blockIdx.x * G1_BM;

    float acc[8][4];
#pragma unroll
    for (int i = 0; i < 8; i++)
#pragma unroll
        for (int j = 0; j < 4; j++) acc[i][j] = 0.f;

    // A-load geometry: thread -> row tid>>1, k-base (tid&1)*8, 8 scalars
    int a_row = tid >> 1;
    int a_kb  = (tid & 1) * 8;
    int gm_a  = m0 + a_row;
    bool a_ok = (gm_a < NN);
    // clamp row pointer so OOB threads issue safe loads (value discarded via a_ok)
    const float* a_ptr = A + (long)(a_ok ? gm_a : 0) * FIN;
    int b_r = tid >> 4;
    int b_c = (tid & 15) * 4;

    // ---- full K tiles: no k-bound checks in the load ----
    for (int k0 = 0; k0 < G1_KFULL; k0 += G1_BK) {
#pragma unroll
        for (int j = 0; j < 8; j++) {
            float v = __ldg(a_ptr + k0 + a_kb + j);
            As[a_kb + j][a_row] = a_ok ? v : 0.f;
        }
        {
            float4 v = *(const float4*)&B[(k0 + b_r) * HID + b_c];
            *(float4*)&Bs[b_r][b_c] = v;
        }
        __syncthreads();
#pragma unroll
        for (int kk = 0; kk < G1_BK; kk++) {
            float4 a0 = *(const float4*)&As[kk][ty * 8];
            float4 a1 = *(const float4*)&As[kk][ty * 8 + 4];
            float4 b4 = *(const float4*)&Bs[kk][tx * 4];
            float a[8] = {a0.x, a0.y, a0.z, a0.w, a1.x, a1.y, a1.z, a1.w};
            float b[4] = {b4.x, b4.y, b4.z, b4.w};
#pragma unroll
            for (int i = 0; i < 8; i++)
#pragma unroll
                for (int j = 0; j < 4; j++) acc[i][j] += a[i] * b[j];
        }
        __syncthreads();
    }

    // ---- epilogue tile: k0 = 1424, 9 valid k ----
    {
        const int k0 = G1_KFULL;
#pragma unroll
        for (int j = 0; j < 8; j++) {
            int gk = k0 + a_kb + j;
            float v = 0.f;
            if (a_ok && gk < FIN) v = __ldg(a_ptr + gk);
            As[a_kb + j][a_row] = v;
        }
        {
            int gk = k0 + b_r;
            float4 v = make_float4(0.f, 0.f, 0.f, 0.f);
            if (gk < FIN) v = *(const float4*)&B[gk * HID + b_c];
            *(float4*)&Bs[b_r][b_c] = v;
        }
        __syncthreads();
#pragma unroll
        for (int kk = 0; kk < G1_BK; kk++) {
            float4 a0 = *(const float4*)&As[kk][ty * 8];
            float4 a1 = *(const float4*)&As[kk][ty * 8 + 4];
            float4 b4 = *(const float4*)&Bs[kk][tx * 4];
            float a[8] = {a0.x, a0.y, a0.z, a0.w, a1.x, a1.y, a1.z, a1.w};
            float b[4] = {b4.x, b4.y, b4.z, b4.w};
#pragma unroll
            for (int i = 0; i < 8; i++)
#pragma unroll
                for (int j = 0; j < 4; j++) acc[i][j] += a[i] * b[j];
        }
    }

#pragma unroll
    for (int i = 0; i < 8; i++) {
        int gm = m0 + ty * 8 + i;
        if (gm < NN) {
            float4 v = make_float4(acc[i][0], acc[i][1], acc[i][2], acc[i][3]);
            *(float4*)&Cout[gm * HID + tx * 4] = v;
        }
    }
}

// ---------------- fine edge propagate: agg[dst] += h0[src]*norm ----------------
__global__ void fine_edge_kernel() {
    int gidx = blockIdx.x * blockDim.x + threadIdx.x;
    int e = gidx >> 4;
    int q = gidx & 15;
    if (e >= EE) return;
    int s = g_ei[e];
    int d = g_ei[EE + e];
    float nrm = g_buf[OFF_DINVF + s] * g_buf[OFF_DINVF + d];
    const float4 v = *(const float4*)&g_buf[OFF_H0 + s * HID + q * 4];
    red4(&g_buf[OFF_AGG + d * HID + q * 4],
         make_float4(v.x * nrm, v.y * nrm, v.z * nrm, v.w * nrm));
}

// ---------------- finalize fine + pool into clusters ----------------
__global__ void finalize_fine_kernel(const float* __restrict__ b_enc) {
    int idx = blockIdx.x * blockDim.x + threadIdx.x;
    int i = idx >> 4;
    int q = idx & 15;
    if (i >= NN) return;
    float id = g_buf[OFF_IDEGF + i];
    float4 a  = *(const float4*)&g_buf[OFF_AGG + i * HID + q * 4];
    float4 h0 = *(const float4*)&g_buf[OFF_H0 + i * HID + q * 4];
    float4 be = *(const float4*)&b_enc[q * 4];
    float4 h;
    h.x = fmaxf(a.x + h0.x * id + be.x, 0.f);
    h.y = fmaxf(a.y + h0.y * id + be.y, 0.f);
    h.z = fmaxf(a.z + h0.z * id + be.z, 0.f);
    h.w = fmaxf(a.w + h0.w * id + be.w, 0.f);
    int c = g_cl[i];
    red4(&g_buf[OFF_XC + c * HID + q * 4], h);
}

// ---------------- coarse edge propagate ----------------
// x_c = xc_sum * icnt folded into the edge weight
__global__ void coarse_edge_kernel() {
    int gidx = blockIdx.x * blockDim.x + threadIdx.x;
    int e = gidx >> 4;
    int q = gidx & 15;
    if (e >= EE) return;
    int sc = g_cl[g_ei[e]];
    int dc = g_cl[g_ei[EE + e]];
    float w = g_buf[OFF_DINVC + sc] * g_buf[OFF_DINVC + dc] * g_buf[OFF_ICNT + sc];
    const float4 v = *(const float4*)&g_buf[OFF_XC + sc * HID + q * 4];
    red4(&g_buf[OFF_AGGC + dc * HID + q * 4],
         make_float4(v.x * w, v.y * w, v.z * w, v.w * w));
}

// ---------------- finalize coarse: tmpc = aggc + x_c/deg_c ----------------
__global__ void finalize_coarse_kernel() {
    int idx = blockIdx.x * blockDim.x + threadIdx.x;
    int c = idx >> 4;
    int q = idx & 15;
    if (c >= CC) return;
    float self_w = g_buf[OFF_ICNT + c] * g_buf[OFF_IDEGC + c];
    float4 a  = *(const float4*)&g_buf[OFF_AGGC + c * HID + q * 4];
    float4 xc = *(const float4*)&g_buf[OFF_XC + c * HID + q * 4];
    float4 r;
    r.x = a.x + xc.x * self_w;
    r.y = a.y + xc.y * self_w;
    r.z = a.z + xc.z * self_w;
    r.w = a.w + xc.w * self_w;
    *(float4*)&g_buf[OFF_TMPC + c * HID + q * 4] = r;
}

// ---------------- GEMM2: xd[C,1433] = tmpc[C,64] @ W_dec[64,1433] + b_dec ----------------
#define G2_BM 32
#define G2_BN 64
__global__ void gemm2_kernel(const float* __restrict__ Wdec,
                             const float* __restrict__ bdec) {
    __shared__ float As[G2_BM][HID + 1];
    __shared__ float Bs[HID][G2_BN];
    const float* A = g_buf + OFF_TMPC;
    float* Cout = g_buf + OFF_XD;

    int tid = threadIdx.x;                 // 256
    int tx = tid & 15;                     // 16 -> 64 cols (4 each)
    int ty = tid >> 4;                     // 16 -> 32 rows (2 each)
    int m0 = blockIdx.y * G2_BM;
    int n0 = blockIdx.x * G2_BN;

    // load A: each thread 8 contiguous floats of one row
    {
        int row = tid >> 3;
        int kb  = (tid & 7) * 8;
        int gm  = m0 + row;
#pragma unroll
        for (int j = 0; j < 8; j++) {
            float v = 0.f;
            if (gm < CC) v = A[gm * HID + kb + j];
            As[row][kb + j] = v;
        }
    }
    // load B: 64x64 tile, col-fastest, scalar (1433-stride rows are unaligned)
    {
#pragma unroll
        for (int r = 0; r < 16; r++) {
            int li = tid + 256 * r;
            int k  = li >> 6;
            int c  = li & 63;
            int gn = n0 + c;
            Bs[k][c] = (gn < FIN) ? Wdec[k * FIN + gn] : 0.f;
        }
    }
    __syncthreads();

    float acc[2][4];
#pragma unroll
    for (int i = 0; i < 2; i++)
#pragma unroll
        for (int j = 0; j < 4; j++) acc[i][j] = 0.f;

#pragma unroll
    for (int k = 0; k < HID; k++) {
        float a0 = As[ty * 2 + 0][k];
        float a1 = As[ty * 2 + 1][k];
        float4 b4 = *(const float4*)&Bs[k][tx * 4];
        acc[0][0] += a0 * b4.x; acc[0][1] += a0 * b4.y;
        acc[0][2] += a0 * b4.z; acc[0][3] += a0 * b4.w;
        acc[1][0] += a1 * b4.x; acc[1][1] += a1 * b4.y;
        acc[1][2] += a1 * b4.z; acc[1][3] += a1 * b4.w;
    }

#pragma unroll
    for (int i = 0; i < 2; i++) {
        int gm = m0 + ty * 2 + i;
        if (gm >= CC) continue;
#pragma unroll
        for (int j = 0; j < 4; j++) {
            int gn = n0 + tx * 4 + j;
            if (gn < FIN) Cout[gm * FIN + gn] = acc[i][j] + bdec[gn];
        }
    }
}

// ---------------- unpool gather: out[i] = xd[cluster[i]] ----------------
__global__ void gather_kernel(float* __restrict__ out) {
    int i = blockIdx.y;
    int f = blockIdx.x * blockDim.x + threadIdx.x;
    if (f >= FIN) return;
    int c = g_cl[i];
    out[(size_t)i * FIN + f] = g_buf[OFF_XD + c * FIN + f];
}

// ---------------- launch ----------------
extern "C" void kernel_launch(void* const* d_in, const int* in_sizes, int n_in,
                              void* d_out, int out_size) {
    const float* x       = (const float*)d_in[0];
    const int*   ei_raw  = (const int*)d_in[1];   // edge_index [2,E] (int32 or int64, sniffed)
    // d_in[2] = batch (unused)
    const int*   cl_raw  = (const int*)d_in[3];
    const float* W_enc   = (const float*)d_in[4];
    const float* b_enc   = (const float*)d_in[5];
    const float* W_dec   = (const float*)d_in[6];
    const float* b_dec   = (const float*)d_in[7];
    float* out = (float*)d_out;

    const int T = 256;

    detect_kernel<<<1, 32>>>(ei_raw);
    convert_edges_kernel<<<(2 * EE + T - 1) / T, T>>>(ei_raw);
    convert_cluster_kernel<<<(NN + T - 1) / T, T>>>(cl_raw);

    zero_kernel<<<(ZERO_TOT / 4 + T - 1) / T, T>>>();
    count_edges_kernel<<<(EE / 4 + T - 1) / T, T>>>();
    node_pass_kernel<<<(NN + T - 1) / T, T>>>();
    prep_kernel<<<(NN + T - 1) / T, T>>>();

    gemm1_kernel<<<(NN + G1_BM - 1) / G1_BM, T>>>(x, W_enc);

    long fine_threads = (long)EE * 16;
    fine_edge_kernel<<<(int)((fine_threads + T - 1) / T), T>>>();

    finalize_fine_kernel<<<(NN * 16 + T - 1) / T, T>>>(b_enc);

    coarse_edge_kernel<<<(int)((fine_threads + T - 1) / T), T>>>();

    finalize_coarse_kernel<<<(CC * 16 + T - 1) / T, T>>>();

    dim3 g2_grid((FIN + G2_BN - 1) / G2_BN, (CC + G2_BM - 1) / G2_BM);
    gemm2_kernel<<<g2_grid, T>>>(W_dec, b_dec);

    dim3 gather_grid((FIN + T - 1) / T, NN);
    gather_kernel<<<gather_grid, T>>>(out);
}

// round 11
// speedup vs baseline: 1.1952x; 1.1952x over previous
#include <cuda_runtime.h>
#include <cstdint>

#define NN  50000
#define EE  1600000
#define FIN 1433
#define HID 64
#define CC  5000

// ---------------- scratch layout (floats) ----------------
#define OFF_AGG   0                         // [NN*64]  fine aggregation (zeroed)
#define OFF_XC    3200000                   // [CC*64]  pooled sums       (zeroed)
#define OFF_AGGC  3520000                   // [CC*64]  coarse agg        (zeroed)
#define OFF_DEGF  3840000                   // [NN]     fine in-degree    (zeroed)
#define OFF_DEGC  3890000                   // [CC]     coarse in-degree  (zeroed)
#define OFF_CNT   3895000                   // [CC]     cluster counts    (zeroed)
#define ZERO_TOT  3900000
#define OFF_H0    3900000                   // [NN*64]  x @ W_enc
#define OFF_DINVF 7100000                   // [NN]
#define OFF_IDEGF 7150000                   // [NN]
#define OFF_DINVC 7200000                   // [CC]
#define OFF_IDEGC 7205000                   // [CC]
#define OFF_ICNT  7210000                   // [CC]
#define OFF_TMPC  7215000                   // [CC*64]  coarse propagate out
#define OFF_XD    7535000                   // [CC*FIN] decoded coarse features
#define TOTAL_F   14700000                  // ~58.8 MB

__device__ __align__(128) float g_buf[TOTAL_F];
__device__ __align__(128) int   g_ei[2 * EE];   // converted int32 edge index
__device__ __align__(128) int   g_cl[NN];       // converted int32 cluster
__device__ int g_is64;                          // 1 if inputs are int64

// non-returning vector reduction to global (L2 atomic, 16B)
__device__ __forceinline__ void red4(float* p, float4 v) {
    asm volatile("red.global.add.v4.f32 [%0], {%1,%2,%3,%4};"
                 :: "l"(p), "f"(v.x), "f"(v.y), "f"(v.z), "f"(v.w) : "memory");
}

__device__ __forceinline__ uint32_t f2tf32(float f) {
    uint32_t u;
    asm("cvt.rna.tf32.f32 %0, %1;" : "=r"(u) : "f"(f));
    return u;
}

__device__ __forceinline__ void mma_tf32(float* c, const uint32_t* a, const uint32_t* b) {
    asm volatile("mma.sync.aligned.m16n8k8.row.col.f32.tf32.tf32.f32 "
        "{%0,%1,%2,%3}, {%4,%5,%6,%7}, {%8,%9}, {%0,%1,%2,%3};"
        : "+f"(c[0]), "+f"(c[1]), "+f"(c[2]), "+f"(c[3])
        : "r"(a[0]), "r"(a[1]), "r"(a[2]), "r"(a[3]), "r"(b[0]), "r"(b[1]));
}

// ---------------- dtype sniff: int64 layout has zero high words ----------------
__global__ void detect_kernel(const int* __restrict__ ei_raw) {
    if (threadIdx.x == 0 && blockIdx.x == 0) {
        int all_zero = 1;
        for (int k = 0; k < 64; k++) {
            if (ei_raw[2 * k + 1] != 0) { all_zero = 0; break; }
        }
        g_is64 = all_zero;
    }
}

// convert + fused degree count: dst-half entries bump DEGF (zeroed beforehand)
__global__ void convert_edges_kernel(const int* __restrict__ ei_raw) {
    int i = blockIdx.x * blockDim.x + threadIdx.x;
    if (i >= 2 * EE) return;
    int f = g_is64;
    int v = f ? ei_raw[2 * i] : ei_raw[i];
    g_ei[i] = v;
    if (i >= EE) atomicAdd(&g_buf[OFF_DEGF + v], 1.0f);
}

// ---------------- zero scratch ----------------
__global__ void zero_kernel() {
    int i = blockIdx.x * blockDim.x + threadIdx.x;
    if (i < ZERO_TOT / 4) {
        ((float4*)g_buf)[i] = make_float4(0.f, 0.f, 0.f, 0.f);
    }
}

// fused: convert cluster + deg_c[c] += deg_f[i] + cnt[c] += 1
__global__ void node_pass_kernel(const int* __restrict__ cl_raw) {
    int i = blockIdx.x * blockDim.x + threadIdx.x;
    if (i >= NN) return;
    int f = g_is64;
    int c = f ? cl_raw[2 * i] : cl_raw[i];
    g_cl[i] = c;
    atomicAdd(&g_buf[OFF_DEGC + c], g_buf[OFF_DEGF + i]);
    atomicAdd(&g_buf[OFF_CNT + c], 1.0f);
}

__global__ void prep_kernel() {
    int i = blockIdx.x * blockDim.x + threadIdx.x;
    if (i < NN) {
        float deg = g_buf[OFF_DEGF + i] + 1.0f;
        g_buf[OFF_DINVF + i] = rsqrtf(deg);
        g_buf[OFF_IDEGF + i] = 1.0f / deg;
    }
    if (i < CC) {
        float degc = g_buf[OFF_DEGC + i] + 1.0f;
        g_buf[OFF_DINVC + i] = rsqrtf(degc);
        g_buf[OFF_IDEGC + i] = 1.0f / degc;
        g_buf[OFF_ICNT + i]  = 1.0f / fmaxf(g_buf[OFF_CNT + i], 1.0f);
    }
}

// ---------------- GEMM1 (tf32 tensor): h0[N,64] = x[N,1433] @ W_enc[1433,64] ----
// 128x64 block tile, BK=32, 8 warps in 4(m) x 2(n); warp tile 32x32.
// mma.m16n8k8: per warp 2 m-tiles x 4 n-tiles.
#define TG_BM 128
#define TG_BK 32
#define LDA 36          // As row stride (words): banks (4g+t) bijective -> conflict-free
#define LDB 72          // Bs row stride (words): banks (8t+g) bijective -> conflict-free
#define TG_KFULL 1408   // 44 full BK tiles; tail = 25

__global__ void __launch_bounds__(256, 2) gemm1_tf32_kernel(const float* __restrict__ A,
                                                            const float* __restrict__ B) {
    __shared__ uint32_t As[TG_BM * LDA];
    __shared__ uint32_t Bs[TG_BK * LDB];
    float* Cout = g_buf + OFF_H0;

    int tid  = threadIdx.x;
    int warp = tid >> 5, lane = tid & 31;
    int g = lane >> 2, t = lane & 3;
    int m0 = blockIdx.x * TG_BM;
    int wm = (warp >> 1) * 32;   // warp row offset in tile
    int wn = (warp & 1) * 32;    // warp col offset

    float acc[2][4][4];
#pragma unroll
    for (int i = 0; i < 2; i++)
#pragma unroll
        for (int j = 0; j < 4; j++)
#pragma unroll
            for (int k = 0; k < 4; k++) acc[i][j][k] = 0.f;

    // A-load: 2 threads per row, 16 consecutive floats each
    int a_row = tid >> 1;
    int a_cb  = (tid & 1) * 16;
    int gm_a  = m0 + a_row;
    bool a_ok = (gm_a < NN);
    const float* a_ptr = A + (long)(a_ok ? gm_a : 0) * FIN;

    for (int k0 = 0; k0 < TG_KFULL; k0 += TG_BK) {
        // ---- fill As (cvt to tf32) ----
#pragma unroll
        for (int jj = 0; jj < 4; jj++) {
            uint32_t u[4];
#pragma unroll
            for (int q = 0; q < 4; q++) {
                float v = a_ok ? __ldg(a_ptr + k0 + a_cb + jj * 4 + q) : 0.f;
                u[q] = f2tf32(v);
            }
            *(uint4*)&As[a_row * LDA + a_cb + jj * 4] = make_uint4(u[0], u[1], u[2], u[3]);
        }
        // ---- fill Bs ----
#pragma unroll
        for (int j = 0; j < 2; j++) {
            int i  = tid * 2 + j;
            int bk = i >> 4;
            int bn = (i & 15) * 4;
            float4 v = *(const float4*)&B[(k0 + bk) * HID + bn];
            *(uint4*)&Bs[bk * LDB + bn] =
                make_uint4(f2tf32(v.x), f2tf32(v.y), f2tf32(v.z), f2tf32(v.w));
        }
        __syncthreads();

#pragma unroll
        for (int ks = 0; ks < TG_BK; ks += 8) {
            uint32_t af[2][4], bf[4][2];
#pragma unroll
            for (int mt = 0; mt < 2; mt++) {
                int r = wm + mt * 16;
                af[mt][0] = As[(r + g)     * LDA + ks + t];
                af[mt][1] = As[(r + g + 8) * LDA + ks + t];
                af[mt][2] = As[(r + g)     * LDA + ks + t + 4];
                af[mt][3] = As[(r + g + 8) * LDA + ks + t + 4];
            }
#pragma unroll
            for (int nt = 0; nt < 4; nt++) {
                int c = wn + nt * 8 + g;
                bf[nt][0] = Bs[(ks + t)     * LDB + c];
                bf[nt][1] = Bs[(ks + t + 4) * LDB + c];
            }
#pragma unroll
            for (int mt = 0; mt < 2; mt++)
#pragma unroll
                for (int nt = 0; nt < 4; nt++)
                    mma_tf32(acc[mt][nt], af[mt], bf[nt]);
        }
        __syncthreads();
    }

    // ---- K tail: k0 = 1408, 25 valid ----
    {
        const int k0 = TG_KFULL;
#pragma unroll
        for (int jj = 0; jj < 4; jj++) {
            uint32_t u[4];
#pragma unroll
            for (int q = 0; q < 4; q++) {
                int gk = k0 + a_cb + jj * 4 + q;
                float v = (a_ok && gk < FIN) ? __ldg(a_ptr + gk) : 0.f;
                u[q] = f2tf32(v);
            }
            *(uint4*)&As[a_row * LDA + a_cb + jj * 4] = make_uint4(u[0], u[1], u[2], u[3]);
        }
#pragma unroll
        for (int j = 0; j < 2; j++) {
            int i  = tid * 2 + j;
            int bk = i >> 4;
            int bn = (i & 15) * 4;
            float4 v = make_float4(0.f, 0.f, 0.f, 0.f);
            if (k0 + bk < FIN) v = *(const float4*)&B[(k0 + bk) * HID + bn];
            *(uint4*)&Bs[bk * LDB + bn] =
                make_uint4(f2tf32(v.x), f2tf32(v.y), f2tf32(v.z), f2tf32(v.w));
        }
        __syncthreads();
#pragma unroll
        for (int ks = 0; ks < TG_BK; ks += 8) {
            uint32_t af[2][4], bf[4][2];
#pragma unroll
            for (int mt = 0; mt < 2; mt++) {
                int r = wm + mt * 16;
                af[mt][0] = As[(r + g)     * LDA + ks + t];
                af[mt][1] = As[(r + g + 8) * LDA + ks + t];
                af[mt][2] = As[(r + g)     * LDA + ks + t + 4];
                af[mt][3] = As[(r + g + 8) * LDA + ks + t + 4];
            }
#pragma unroll
            for (int nt = 0; nt < 4; nt++) {
                int c = wn + nt * 8 + g;
                bf[nt][0] = Bs[(ks + t)     * LDB + c];
                bf[nt][1] = Bs[(ks + t + 4) * LDB + c];
            }
#pragma unroll
            for (int mt = 0; mt < 2; mt++)
#pragma unroll
                for (int nt = 0; nt < 4; nt++)
                    mma_tf32(acc[mt][nt], af[mt], bf[nt]);
        }
    }

    // ---- store: c0,c1 at (row g, cols 2t,2t+1); c2,c3 at row g+8 ----
#pragma unroll
    for (int mt = 0; mt < 2; mt++) {
#pragma unroll
        for (int nt = 0; nt < 4; nt++) {
            int col = wn + nt * 8 + 2 * t;
            int r0  = m0 + wm + mt * 16 + g;
            int r1  = r0 + 8;
            if (r0 < NN)
                *(float2*)&Cout[r0 * HID + col] = make_float2(acc[mt][nt][0], acc[mt][nt][1]);
            if (r1 < NN)
                *(float2*)&Cout[r1 * HID + col] = make_float2(acc[mt][nt][2], acc[mt][nt][3]);
        }
    }
}

// ---------------- fine edge propagate: agg[dst] += h0[src]*norm ----------------
__global__ void fine_edge_kernel() {
    int gidx = blockIdx.x * blockDim.x + threadIdx.x;
    int e = gidx >> 4;
    int q = gidx & 15;
    if (e >= EE) return;
    int s = g_ei[e];
    int d = g_ei[EE + e];
    float nrm = g_buf[OFF_DINVF + s] * g_buf[OFF_DINVF + d];
    const float4 v = *(const float4*)&g_buf[OFF_H0 + s * HID + q * 4];
    red4(&g_buf[OFF_AGG + d * HID + q * 4],
         make_float4(v.x * nrm, v.y * nrm, v.z * nrm, v.w * nrm));
}

// ---------------- finalize fine + pool into clusters ----------------
__global__ void finalize_fine_kernel(const float* __restrict__ b_enc) {
    int idx = blockIdx.x * blockDim.x + threadIdx.x;
    int i = idx >> 4;
    int q = idx & 15;
    if (i >= NN) return;
    float id = g_buf[OFF_IDEGF + i];
    float4 a  = *(const float4*)&g_buf[OFF_AGG + i * HID + q * 4];
    float4 h0 = *(const float4*)&g_buf[OFF_H0 + i * HID + q * 4];
    float4 be = *(const float4*)&b_enc[q * 4];
    float4 h;
    h.x = fmaxf(a.x + h0.x * id + be.x, 0.f);
    h.y = fmaxf(a.y + h0.y * id + be.y, 0.f);
    h.z = fmaxf(a.z + h0.z * id + be.z, 0.f);
    h.w = fmaxf(a.w + h0.w * id + be.w, 0.f);
    int c = g_cl[i];
    red4(&g_buf[OFF_XC + c * HID + q * 4], h);
}

// ---------------- coarse edge propagate ----------------
__global__ void coarse_edge_kernel() {
    int gidx = blockIdx.x * blockDim.x + threadIdx.x;
    int e = gidx >> 4;
    int q = gidx & 15;
    if (e >= EE) return;
    int sc = g_cl[g_ei[e]];
    int dc = g_cl[g_ei[EE + e]];
    float w = g_buf[OFF_DINVC + sc] * g_buf[OFF_DINVC + dc] * g_buf[OFF_ICNT + sc];
    const float4 v = *(const float4*)&g_buf[OFF_XC + sc * HID + q * 4];
    red4(&g_buf[OFF_AGGC + dc * HID + q * 4],
         make_float4(v.x * w, v.y * w, v.z * w, v.w * w));
}

// ---------------- finalize coarse: tmpc = aggc + x_c/deg_c ----------------
__global__ void finalize_coarse_kernel() {
    int idx = blockIdx.x * blockDim.x + threadIdx.x;
    int c = idx >> 4;
    int q = idx & 15;
    if (c >= CC) return;
    float self_w = g_buf[OFF_ICNT + c] * g_buf[OFF_IDEGC + c];
    float4 a  = *(const float4*)&g_buf[OFF_AGGC + c * HID + q * 4];
    float4 xc = *(const float4*)&g_buf[OFF_XC + c * HID + q * 4];
    float4 r;
    r.x = a.x + xc.x * self_w;
    r.y = a.y + xc.y * self_w;
    r.z = a.z + xc.z * self_w;
    r.w = a.w + xc.w * self_w;
    *(float4*)&g_buf[OFF_TMPC + c * HID + q * 4] = r;
}

// ---------------- GEMM2: xd[C,1433] = tmpc[C,64] @ W_dec[64,1433] + b_dec ----------------
#define G2_BM 32
#define G2_BN 64
__global__ void gemm2_kernel(const float* __restrict__ Wdec,
                             const float* __restrict__ bdec) {
    __shared__ float As2[G2_BM][HID + 1];
    __shared__ float Bs2[HID][G2_BN];
    const float* A = g_buf + OFF_TMPC;
    float* Cout = g_buf + OFF_XD;

    int tid = threadIdx.x;                 // 256
    int tx = tid & 15;
    int ty = tid >> 4;
    int m0 = blockIdx.y * G2_BM;
    int n0 = blockIdx.x * G2_BN;

    {
        int row = tid >> 3;
        int kb  = (tid & 7) * 8;
        int gm  = m0 + row;
#pragma unroll
        for (int j = 0; j < 8; j++) {
            float v = 0.f;
            if (gm < CC) v = A[gm * HID + kb + j];
            As2[row][kb + j] = v;
        }
    }
    {
#pragma unroll
        for (int r = 0; r < 16; r++) {
            int li = tid + 256 * r;
            int k  = li >> 6;
            int c  = li & 63;
            int gn = n0 + c;
            Bs2[k][c] = (gn < FIN) ? Wdec[k * FIN + gn] : 0.f;
        }
    }
    __syncthreads();

    float acc[2][4];
#pragma unroll
    for (int i = 0; i < 2; i++)
#pragma unroll
        for (int j = 0; j < 4; j++) acc[i][j] = 0.f;

#pragma unroll
    for (int k = 0; k < HID; k++) {
        float a0 = As2[ty * 2 + 0][k];
        float a1 = As2[ty * 2 + 1][k];
        float4 b4 = *(const float4*)&Bs2[k][tx * 4];
        acc[0][0] += a0 * b4.x; acc[0][1] += a0 * b4.y;
        acc[0][2] += a0 * b4.z; acc[0][3] += a0 * b4.w;
        acc[1][0] += a1 * b4.x; acc[1][1] += a1 * b4.y;
        acc[1][2] += a1 * b4.z; acc[1][3] += a1 * b4.w;
    }

#pragma unroll
    for (int i = 0; i < 2; i++) {
        int gm = m0 + ty * 2 + i;
        if (gm >= CC) continue;
#pragma unroll
        for (int j = 0; j < 4; j++) {
            int gn = n0 + tx * 4 + j;
            if (gn < FIN) Cout[gm * FIN + gn] = acc[i][j] + bdec[gn];
        }
    }
}

// ---------------- unpool gather (flattened): out[idx] = xd[cluster[idx/FIN]*FIN + idx%FIN]
// magic divide by 1433: i = (idx * 1534559146) >> 41, exact for all idx < NN*FIN
#define GATH_TOT (NN * FIN)
__global__ void gather_kernel(float* __restrict__ out) {
    int idx = blockIdx.x * blockDim.x + threadIdx.x;
    if (idx >= GATH_TOT) return;
    unsigned i = (unsigned)(((unsigned long long)(unsigned)idx * 1534559146ULL) >> 41);
    int f = idx - (int)i * FIN;
    int c = g_cl[i];
    out[idx] = g_buf[OFF_XD + c * FIN + f];
}

// ---------------- launch ----------------
extern "C" void kernel_launch(void* const* d_in, const int* in_sizes, int n_in,
                              void* d_out, int out_size) {
    const float* x       = (const float*)d_in[0];
    const int*   ei_raw  = (const int*)d_in[1];
    const int*   cl_raw  = (const int*)d_in[3];
    const float* W_enc   = (const float*)d_in[4];
    const float* b_enc   = (const float*)d_in[5];
    const float* W_dec   = (const float*)d_in[6];
    const float* b_dec   = (const float*)d_in[7];
    float* out = (float*)d_out;

    const int T = 256;

    detect_kernel<<<1, 32>>>(ei_raw);
    zero_kernel<<<(ZERO_TOT / 4 + T - 1) / T, T>>>();          // zero DEGF BEFORE fused count
    convert_edges_kernel<<<(2 * EE + T - 1) / T, T>>>(ei_raw); // convert + count degrees

    node_pass_kernel<<<(NN + T - 1) / T, T>>>(cl_raw);         // convert cluster + coarse degrees
    prep_kernel<<<(NN + T - 1) / T, T>>>();

    gemm1_tf32_kernel<<<(NN + TG_BM - 1) / TG_BM, T>>>(x, W_enc);

    long fine_threads = (long)EE * 16;
    fine_edge_kernel<<<(int)((fine_threads + T - 1) / T), T>>>();

    finalize_fine_kernel<<<(NN * 16 + T - 1) / T, T>>>(b_enc);

    coarse_edge_kernel<<<(int)((fine_threads + T - 1) / T), T>>>();

    finalize_coarse_kernel<<<(CC * 16 + T - 1) / T, T>>>();

    dim3 g2_grid((FIN + G2_BN - 1) / G2_BN, (CC + G2_BM - 1) / G2_BM);
    gemm2_kernel<<<g2_grid, T>>>(W_dec, b_dec);

    gather_kernel<<<(GATH_TOT + T - 1) / T, T>>>(out);
}